// round 17
// baseline (speedup 1.0000x reference)
#include <cuda_runtime.h>

#define L  4096
#define V  50257
#define H1 30
#define H2 50
#define G1 120   // 4*H1
#define G2 200   // 4*H2
#define TCHUNK 1024
#define SCAN_DYN_SMEM (200*1024)

// scratch (device globals: no allocation allowed)
__device__ float g_gx1p[L * 128];   // [t][cell*4 + gate], row padded to 128
__device__ float g_h1r [L * 32];    // layer1 hidden, row padded to 32 (1 line/row)
__device__ float g_gx2p[L * 256];   // factory output: [t][gate j], row padded to 256
__device__ float g_h2p [L * 64];    // layer2 hidden, row padded to 64 (2 lines/row)
__device__ float g_wf  [G2 * H1];   // W_ih2 @ W1
__device__ float g_bf  [G2];        // W_ih2 @ bl1 + b_ih2 + b_hh2
__device__ float g_c1  [32];        // layer1 cell state between scan parts
__device__ float g_c2  [224];       // layer2 cell state between scan parts
__device__ int   g_prog;            // #h1 rows published (layer1 -> factory)
__device__ int   g_prog3;           // #gx2 rows published (factory -> layer2)

typedef unsigned long long u64;

__device__ __forceinline__ u64 pk2(float lo, float hi) {
    u64 r; asm("mov.b64 %0, {%1, %2};" : "=l"(r) : "f"(lo), "f"(hi)); return r;
}
__device__ __forceinline__ u64 ffma2(u64 a, u64 b, u64 c) {
    u64 d; asm("fma.rn.f32x2 %0, %1, %2, %3;" : "=l"(d) : "l"(a), "l"(b), "l"(c)); return d;
}
__device__ __forceinline__ u64 fadd2(u64 a, u64 b) {
    u64 d; asm("add.rn.f32x2 %0, %1, %2;" : "=l"(d) : "l"(a), "l"(b)); return d;
}
__device__ __forceinline__ float hsum2(u64 a) {
    float x, y; asm("mov.b64 {%0, %1}, %2;" : "=f"(x), "=f"(y) : "l"(a)); return x + y;
}

__device__ __forceinline__ float fexp(float x) {
    float y; asm("ex2.approx.f32 %0, %1;" : "=f"(y) : "f"(x * 1.4426950408889634f)); return y;
}
__device__ __forceinline__ float frcp(float x) {
    float y; asm("rcp.approx.f32 %0, %1;" : "=f"(y) : "f"(x)); return y;
}
__device__ __forceinline__ float sigm(float x)   { return frcp(1.0f + fexp(-x)); }
__device__ __forceinline__ float tanh_f(float x) { return 1.0f - 2.0f * frcp(fexp(2.0f * x) + 1.0f); }

__device__ __forceinline__ int ld_acq(const int* p) {
    int v; asm volatile("ld.global.acquire.gpu.s32 %0, [%1];" : "=r"(v) : "l"(p) : "memory");
    return v;
}
__device__ __forceinline__ void st_rel(int* p, int v) {
    asm volatile("st.global.release.gpu.s32 [%0], %1;" :: "l"(p), "r"(v) : "memory");
}
// L2-coherent loads (bypass non-coherent L1) for cross-CTA streamed data
__device__ __forceinline__ float4 ldcg4(const float4* p) {
    float4 v;
    asm volatile("ld.global.cg.v4.f32 {%0,%1,%2,%3}, [%4];"
                 : "=f"(v.x), "=f"(v.y), "=f"(v.z), "=f"(v.w) : "l"(p) : "memory");
    return v;
}
__device__ __forceinline__ float ldcg1(const float* p) {
    float v;
    asm volatile("ld.global.cg.f32 %0, [%1];" : "=f"(v) : "l"(p) : "memory");
    return v;
}

// ---------------------------------------------------------------------------
// K1: gx1p[t][c*4+g] = emb[x[t]] . w_ih1[g*30+c] + b_ih1 + b_hh1 (pad -> 0)
// Also resets the progress flags.
// ---------------------------------------------------------------------------
__global__ void k_gx1(const int* __restrict__ x, const float* __restrict__ emb,
                      const float* __restrict__ w_ih1, const float* __restrict__ b_ih1,
                      const float* __restrict__ b_hh1) {
    int idx = blockIdx.x * blockDim.x + threadIdx.x;
    if (idx == 0) { g_prog = 0; g_prog3 = 0; }
    if (idx >= L * 128) return;
    int t = idx >> 7, jj = idx & 127;
    int c = jj >> 2, g = jj & 3;
    float s = 0.0f;
    if (c < H1) {
        int j = g * H1 + c;
        const float* er = emb + (long)x[t] * H1;
        const float* wr = w_ih1 + j * H1;
        s = b_ih1[j] + b_hh1[j];
#pragma unroll
        for (int k = 0; k < H1; k++) s += er[k] * wr[k];
    }
    g_gx1p[idx] = s;
}

// ---------------------------------------------------------------------------
// K2: fuse Wf = W_ih2 @ W1, bf = W_ih2 @ bl1 + b_ih2 + b_hh2
// ---------------------------------------------------------------------------
__global__ void k_fuse(const float* __restrict__ w_ih2, const float* __restrict__ w1,
                       const float* __restrict__ bl1, const float* __restrict__ b_ih2,
                       const float* __restrict__ b_hh2) {
    int idx = blockIdx.x * blockDim.x + threadIdx.x;
    if (idx < G2 * H1) {
        int j = idx / H1, m = idx % H1;
        float s = 0.0f;
#pragma unroll
        for (int k = 0; k < H2; k++) s += w_ih2[j * H2 + k] * w1[k * H1 + m];
        g_wf[idx] = s;
    }
    if (idx < G2) {
        float s = b_ih2[idx] + b_hh2[idx];
#pragma unroll
        for (int k = 0; k < H2; k++) s += w_ih2[idx * H2 + k] * bl1[k];
        g_bf[idx] = s;
    }
}

// ---------------------------------------------------------------------------
// K3: scan over [t0, t1) — THREE cooperating CTAs (each SM-exclusive, 200KB):
//   blockIdx 1 : layer1 (1 warp). Publishes g_prog every 8 steps.
//   blockIdx 2 : gx2 FACTORY (8 warps). Trails layer1 by <=8 rows; computes
//                gx2[n] = Wf.h1[n] + bf; publishes g_prog3 every 8 rows.
//   blockIdx 0 : layer2 (warps 0-6 gates, warp 7 = prog3 poll every 16 steps).
//                Gate threads prefetch their gx2 scalar 2 steps ahead; only
//                the 50-wide recurrent dot remains in the step.
// ---------------------------------------------------------------------------
__global__ void __launch_bounds__(256, 1) k_scan(const float* __restrict__ w_hh1,
                                                 const float* __restrict__ w_hh2,
                                                 int t0, int t1) {
    extern __shared__ __align__(16) float sbuf[];
    const int tid = threadIdx.x, wid = tid >> 5, lane = tid & 31;

    if (blockIdx.x == 1) {
        // ================= layer 1 : single warp =================
        if (wid != 0) return;
        float* h_sh = sbuf;
        const int c = lane;
        const bool valid = (c < H1);

        u64 w[4][15];
#pragma unroll
        for (int g = 0; g < 4; g++)
#pragma unroll
            for (int m = 0; m < 15; m++) w[g][m] = 0;
        if (valid) {
#pragma unroll
            for (int g = 0; g < 4; g++) {
                const float* row = w_hh1 + (g * H1 + c) * H1;
#pragma unroll
                for (int m = 0; m < 15; m++) w[g][m] = pk2(row[2 * m], row[2 * m + 1]);
            }
        }
        float cst;
        if (t0 == 0) { h_sh[lane] = 0.0f; cst = 0.0f; }
        else         { h_sh[lane] = g_h1r[(t0 - 1) * 32 + lane]; cst = g_c1[lane]; }
        __syncwarp();

        float4 gxbuf[2];
        gxbuf[0] = __ldg((const float4*)&g_gx1p[(t0 + 0) * 128 + c * 4]);
        gxbuf[1] = __ldg((const float4*)&g_gx1p[(t0 + 1) * 128 + c * 4]);

        for (int n = t0; n < t1; n++) {
            float4 gx = gxbuf[n & 1];
            if (n + 2 < t1)
                gxbuf[n & 1] = __ldg((const float4*)&g_gx1p[(n + 2) * 128 + c * 4]);

            const u64* hp = (const u64*)h_sh;
            u64 hv[15];
            {
                const ulonglong2* h2p = (const ulonglong2*)h_sh;
#pragma unroll
                for (int m = 0; m < 7; m++) { ulonglong2 t2 = h2p[m]; hv[2*m] = t2.x; hv[2*m+1] = t2.y; }
                hv[14] = hp[14];
            }
            u64 a0[4], a1[4];
#pragma unroll
            for (int g = 0; g < 4; g++) { a0[g] = 0; a1[g] = 0; }
#pragma unroll
            for (int g = 0; g < 4; g++) {
#pragma unroll
                for (int m = 0; m < 15; m += 2) a0[g] = ffma2(w[g][m], hv[m], a0[g]);
#pragma unroll
                for (int m = 1; m < 15; m += 2) a1[g] = ffma2(w[g][m], hv[m], a1[g]);
            }
            float si = gx.x + hsum2(fadd2(a0[0], a1[0]));
            float sf = gx.y + hsum2(fadd2(a0[1], a1[1]));
            float sg = gx.z + hsum2(fadd2(a0[2], a1[2]));
            float so = gx.w + hsum2(fadd2(a0[3], a1[3]));
            float ai = sigm(si), af = sigm(sf), ag = tanh_f(sg), ao = sigm(so);
            cst = af * cst + ai * ag;
            float h = valid ? ao * tanh_f(cst) : 0.0f;
            __syncwarp();
            h_sh[lane] = h;
            g_h1r[n * 32 + lane] = h;
            __syncwarp();
            if ((n & 7) == 7) {
                __threadfence();
                if (lane == 0) st_rel(&g_prog, n + 1);
            }
        }
        g_c1[lane] = cst;
        return;
    }

    if (blockIdx.x == 2) {
        // ================= gx2 factory : 8 warps =================
        float* wfs   = sbuf;            // 200 rows x 32 floats (padded)
        float* bfs   = sbuf + 6400;     // 200 floats
        float* h1buf = sbuf + 6656;     // 8 warps x 32 floats

        // cache Wf (padded rows) + bf in smem
        for (int i = tid; i < G2 * H1; i += 256) {
            int j = i / H1, m = i - j * H1;
            wfs[j * 32 + m] = g_wf[i];
        }
        for (int i = tid; i < G2; i += 256) bfs[i] = g_bf[i];
        __syncthreads();

        for (int m0 = t0; m0 < t1; m0 += 8) {
            int row = m0 + wid;
            if (lane == 0) { while (ld_acq(&g_prog) < row + 1) {} }
            __syncwarp();
            if (lane < 8)
                ((float4*)(h1buf + wid * 32))[lane] =
                    ldcg4((const float4*)&g_h1r[row * 32 + lane * 4]);
            __syncwarp();
            const u64* hp = (const u64*)(h1buf + wid * 32);
            u64 hv[15];
            {
                const ulonglong2* hq = (const ulonglong2*)hp;
#pragma unroll
                for (int q = 0; q < 7; q++) { ulonglong2 t2 = hq[q]; hv[2*q] = t2.x; hv[2*q+1] = t2.y; }
                hv[14] = hp[14];
            }
#pragma unroll
            for (int g = 0; g < 7; g++) {
                int j = g * 32 + lane;
                if (j < G2) {
                    const u64* wrow = (const u64*)(wfs + j * 32);
                    u64 a0 = 0, a1 = 0;
#pragma unroll
                    for (int q = 0; q < 15; q += 2) a0 = ffma2(wrow[q], hv[q], a0);
#pragma unroll
                    for (int q = 1; q < 15; q += 2) a1 = ffma2(wrow[q], hv[q], a1);
                    g_gx2p[row * 256 + j] = bfs[j] + hsum2(fadd2(a0, a1));
                }
            }
            __syncthreads();
            if (tid == 0) { __threadfence(); st_rel(&g_prog3, m0 + 8); }
        }
        return;
    }

    // ================= layer 2 : 8 warps (blockIdx 0) =================
    {
        float* h2s = sbuf;                 // 2 x 56
        const int gate = lane >> 3, sub = lane & 7;
        const bool isGate = (wid < 7);
        const int cell = wid * 8 + sub;
        const bool valid = isGate && (cell < H2);
        const int j = gate * H2 + cell;    // gx2 index

        u64 wc[25];
#pragma unroll
        for (int m = 0; m < 25; m++) wc[m] = 0;
        if (valid) {
            const float* w2r = w_hh2 + j * H2;
#pragma unroll
            for (int m = 0; m < 25; m++) wc[m] = pk2(w2r[2 * m], w2r[2 * m + 1]);
        }
        float cst = 0.0f;
        if (t0 == 0) {
            if (tid < 56) { h2s[tid] = 0.0f; h2s[56 + tid] = 0.0f; }
        } else {
            if (tid < 56) { h2s[tid] = g_h2p[(t0 - 1) * 64 + tid]; h2s[56 + tid] = 0.0f; }
            if (wid < 7) cst = g_c2[wid * 32 + lane];
        }

        // warmup: gx2 rows t0 .. t0+23 available
        if (wid == 7 && lane == 0) {
            int tgt = (t0 + 24 < t1) ? t0 + 24 : t1;
            while (ld_acq(&g_prog3) < tgt) {}
        }
        __syncthreads();

        float gxbuf[2];
        gxbuf[0] = valid ? ldcg1(&g_gx2p[(t0 + 0) * 256 + j]) : 0.0f;
        gxbuf[1] = (valid && t0 + 1 < t1) ? ldcg1(&g_gx2p[(t0 + 1) * 256 + j]) : 0.0f;

        for (int n = t0; n < t1; n++) {
            if (isGate) {
                float gx = gxbuf[n & 1];
                gxbuf[n & 1] = (valid && n + 2 < t1) ? ldcg1(&g_gx2p[(n + 2) * 256 + j]) : 0.0f;

                const u64* hq2 = (const u64*)(h2s + (n & 1) * 56);      // h2[n-1]
                const ulonglong2* hv2 = (const ulonglong2*)hq2;
                u64 a0 = 0, a1 = 0, a2 = 0, a3 = 0;
#pragma unroll
                for (int m = 0; m < 12; m++) {
                    ulonglong2 hh = hv2[m];
                    if ((m & 1) == 0) { a0 = ffma2(wc[2 * m], hh.x, a0); a1 = ffma2(wc[2 * m + 1], hh.y, a1); }
                    else              { a2 = ffma2(wc[2 * m], hh.x, a2); a3 = ffma2(wc[2 * m + 1], hh.y, a3); }
                }
                a0 = ffma2(wc[24], hq2[24], a0);
                float s = gx + hsum2(fadd2(fadd2(a0, a1), fadd2(a2, a3)));
                float act = (gate == 2) ? tanh_f(s) : sigm(s);
                float y1 = __shfl_xor_sync(0xffffffffu, act, 8);
                float y2 = __shfl_xor_sync(0xffffffffu, act, 16);
                float y3 = __shfl_xor_sync(0xffffffffu, act, 24);
                float ai, af, ag, ao;
                if      (gate == 0) { ai = act; af = y1;  ag = y2;  ao = y3;  }
                else if (gate == 1) { ai = y1;  af = act; ag = y3;  ao = y2;  }
                else if (gate == 2) { ai = y2;  af = y3;  ag = act; ao = y1;  }
                else                { ai = y3;  af = y2;  ag = y1;  ao = act; }
                cst = af * cst + ai * ag;
                float h = ao * tanh_f(cst);
                if (gate == 0 && valid) {
                    h2s[((n + 1) & 1) * 56 + cell] = h;
                    g_h2p[n * 64 + cell] = h;
                }
            } else if ((n & 15) == 0) {
                // warp 7: coarse flow control. Poll at n covers gx2 loads of
                // iterations n..n+16 (rows <= n+18) via tgt = n+24.
                if (lane == 0) {
                    int tgt = (n + 24 < t1) ? n + 24 : t1;
                    while (ld_acq(&g_prog3) < tgt) {}
                }
                __syncwarp();
            }
            __syncthreads();
        }
        if (wid < 7) g_c2[wid * 32 + lane] = cst;
    }
}

// ---------------------------------------------------------------------------
// K4: out[t][v] = h2[t] . w2[v] + bl2[v] for t in [tbase + by*256, +256)
// ---------------------------------------------------------------------------
__global__ void k_out(const float* __restrict__ w2, const float* __restrict__ bl2,
                      float* __restrict__ out, int tbase) {
    __shared__ __align__(16) float h_sh[32 * 64];
    int v = blockIdx.x * blockDim.x + threadIdx.x;
    bool active = (v < V);

    u64 wr[25];
    float bias = 0.0f;
    if (active) {
        const float* w = w2 + (long)v * H2;
#pragma unroll
        for (int m = 0; m < 25; m++) wr[m] = pk2(w[2 * m], w[2 * m + 1]);
        bias = bl2[v];
    }

    int tbeg = tbase + blockIdx.y * 256;
    int tend = tbeg + 256;
    for (int t0 = tbeg; t0 < tend; t0 += 32) {
        __syncthreads();
        for (int f = threadIdx.x; f < 512; f += blockDim.x)
            ((float4*)h_sh)[f] = __ldg((const float4*)(g_h2p + t0 * 64) + f);
        __syncthreads();
#pragma unroll 4
        for (int tt = 0; tt < 32; tt++) {
            const u64* hq = (const u64*)(h_sh + tt * 64);
            const ulonglong2* hv = (const ulonglong2*)hq;
            u64 a0 = 0, a1 = 0, a2 = 0, a3 = 0;
#pragma unroll
            for (int m = 0; m < 6; m++) {
                ulonglong2 hh = hv[2 * m];
                a0 = ffma2(wr[4 * m],     hh.x, a0);
                a1 = ffma2(wr[4 * m + 1], hh.y, a1);
                ulonglong2 hh2 = hv[2 * m + 1];
                a2 = ffma2(wr[4 * m + 2], hh2.x, a2);
                a3 = ffma2(wr[4 * m + 3], hh2.y, a3);
            }
            a0 = ffma2(wr[24], hq[24], a0);
            if (active)
                out[(long)(t0 + tt) * V + v] =
                    hsum2(fadd2(fadd2(a0, a1), fadd2(a2, a3))) + bias;
        }
    }
}

// ---------------------------------------------------------------------------
extern "C" void kernel_launch(void* const* d_in, const int* in_sizes, int n_in,
                              void* d_out, int out_size) {
    const int*   x     = (const int*)  d_in[0];
    const float* emb   = (const float*)d_in[1];
    const float* w_ih1 = (const float*)d_in[2];
    const float* w_hh1 = (const float*)d_in[3];
    const float* b_ih1 = (const float*)d_in[4];
    const float* b_hh1 = (const float*)d_in[5];
    const float* w1    = (const float*)d_in[6];
    const float* bl1   = (const float*)d_in[7];
    const float* w_ih2 = (const float*)d_in[8];
    const float* w_hh2 = (const float*)d_in[9];
    const float* b_ih2 = (const float*)d_in[10];
    const float* b_hh2 = (const float*)d_in[11];
    const float* w2    = (const float*)d_in[12];
    const float* bl2   = (const float*)d_in[13];
    float* out = (float*)d_out;

    // one-time setup (no device memory involved)
    static cudaStream_t s2 = nullptr;
    static cudaEvent_t evS[4], evJ;
    if (s2 == nullptr) {
        cudaStreamCreateWithFlags(&s2, cudaStreamNonBlocking);
        for (int i = 0; i < 4; i++)
            cudaEventCreateWithFlags(&evS[i], cudaEventDisableTiming);
        cudaEventCreateWithFlags(&evJ, cudaEventDisableTiming);
        cudaFuncSetAttribute(k_scan, cudaFuncAttributeMaxDynamicSharedMemorySize,
                             SCAN_DYN_SMEM);
    }

    k_gx1 <<<(L * 128 + 255) / 256, 256>>>(x, emb, w_ih1, b_ih1, b_hh1);
    k_fuse<<<(G2 * H1 + 255) / 256, 256>>>(w_ih2, w1, bl1, b_ih2, b_hh2);

    dim3 gout((V + 127) / 128, 4);
    for (int p = 0; p < 4; p++) {
        int t0 = p * TCHUNK, t1 = t0 + TCHUNK;
        k_scan<<<3, 256, SCAN_DYN_SMEM>>>(w_hh1, w_hh2, t0, t1);
        cudaEventRecord(evS[p], 0);
        cudaStreamWaitEvent(s2, evS[p], 0);
        k_out<<<gout, 128, 0, s2>>>(w2, bl2, out, t0);
    }
    cudaEventRecord(evJ, s2);
    cudaStreamWaitEvent(0, evJ, 0);
}